// round 6
// baseline (speedup 1.0000x reference)
#include <cuda_runtime.h>
#include <cstdint>

// ---------------------------------------------------------------------------
// GlobalFusion: sparse->dense scatter fusion, DIM=96, C=24.
// Outputs (f32, concatenated in tuple order):
//   updated_mask   [96^3]            off 0
//   current_volume [96^3 * 24]       off 884736
//   global_volume  [96^3 * 24]       off 22118400
//   target_volume  [96^3]            off 43352064
//   valid          [300000]          off 44236800
//   valid_target   [200000]          off 44536800
//   near_mask      [300000]          off 44736800
//
// R5 structure (revert of memset experiment, back to coalesced resolve):
//   stream0: init -> scat1(cur+tgt fused) -> resolve_cv (85MB, coalesced)
//   sB:      (after scat1) glb -> resolve_gv+upd+tv (92MB, coalesced)
//   join.
// ---------------------------------------------------------------------------

#define DIMV   96
#define NCELLS (96 * 96 * 96)   // 884736
#define NC4    6                // 24 floats = 6 float4
#define N_CUR  150000
#define N_GLB  300000
#define N_TGT  100000
#define N_GTGT 200000

#define OFF_UPD 0
#define OFF_CV  884736
#define OFF_GV  22118400
#define OFF_TV  43352064
#define OFF_VAL 44236800
#define OFF_VT  44536800
#define OFF_NR  44736800

// Scratch (static device globals; no allocation allowed)
__device__ int           g_cur_win[NCELLS];
__device__ int           g_glb_win[NCELLS];
__device__ int           g_tgt_win[NCELLS];
__device__ unsigned char g_valid_vol[NCELLS];
__device__ unsigned char g_occ[NCELLS];

// --------------------------------------------------------------------------
// 1) reset scratch (int4-vectorized)
// --------------------------------------------------------------------------
__global__ void k_init()
{
    int i = blockIdx.x * blockDim.x + threadIdx.x;           // NCELLS/4 threads
    if (i < NCELLS / 4) {
        int4 m1 = make_int4(-1, -1, -1, -1);
        reinterpret_cast<int4*>(g_cur_win)[i] = m1;
        reinterpret_cast<int4*>(g_glb_win)[i] = m1;
        reinterpret_cast<int4*>(g_tgt_win)[i] = m1;
        reinterpret_cast<uint*>(g_valid_vol)[i] = 0u;
        reinterpret_cast<uint*>(g_occ)[i] = 0u;
    }
}

// --------------------------------------------------------------------------
// 2) fused scatter: current-fragment rows + both target scatters.
//    JAX sequential-scatter semantics (last duplicate row wins) -> atomicMax
//    on row index; current-fragment target gets priority N_GTGT+j so it
//    always beats the global target (torch cat order).
// --------------------------------------------------------------------------
__global__ void k_scat1(const int* __restrict__ cc,
                        const int* __restrict__ grid_mask,
                        const int* __restrict__ occupancy,
                        const int* __restrict__ gct,
                        const int* __restrict__ ct,
                        const int* __restrict__ org,
                        float* __restrict__ out_vt)
{
    int i = blockIdx.x * blockDim.x + threadIdx.x;

    if (i < N_CUR) {
        int x = cc[3 * i + 0];
        int y = cc[3 * i + 1];
        int z = cc[3 * i + 2];
        int cell = (x * DIMV + y) * DIMV + z;
        if (grid_mask[i]) g_valid_vol[cell] = 1;
        if (occupancy[i]) g_occ[cell] = 1;
        atomicMax(&g_cur_win[cell], i);
        return;
    }
    int t = i - N_CUR;
    if (t < N_GTGT) {
        int ox = __ldg(&org[0]), oy = __ldg(&org[1]), oz = __ldg(&org[2]);
        int x = gct[3 * t + 0] - ox;
        int y = gct[3 * t + 1] - oy;
        int z = gct[3 * t + 2] - oz;
        bool inb = ((unsigned)x < DIMV) && ((unsigned)y < DIMV) && ((unsigned)z < DIMV);
        out_vt[t] = inb ? 1.0f : 0.0f;
        if (inb) atomicMax(&g_tgt_win[(x * DIMV + y) * DIMV + z], t);
        return;
    }
    int j = t - N_GTGT;
    if (j < N_TGT) {
        int x = ct[3 * j + 0];
        int y = ct[3 * j + 1];
        int z = ct[3 * j + 2];
        atomicMax(&g_tgt_win[(x * DIMV + y) * DIMV + z], N_GTGT + j);
    }
}

// --------------------------------------------------------------------------
// 3) global-fragment rows: bounds + visibility gather, valid/near, glb winner
// --------------------------------------------------------------------------
__global__ void k_glb(const int* __restrict__ gc,
                      const int* __restrict__ org,
                      float* __restrict__ out_valid,
                      float* __restrict__ out_near)
{
    int i = blockIdx.x * blockDim.x + threadIdx.x;
    if (i >= N_GLB) return;
    int ox = __ldg(&org[0]), oy = __ldg(&org[1]), oz = __ldg(&org[2]);
    int x = gc[3 * i + 0] - ox;
    int y = gc[3 * i + 1] - oy;
    int z = gc[3 * i + 2] - oz;
    bool inb = ((unsigned)x < DIMV) && ((unsigned)y < DIMV) && ((unsigned)z < DIMV);
    bool valid = false;
    if (inb) {
        int cell = (x * DIMV + y) * DIMV + z;
        valid = (g_valid_vol[cell] != 0);
        if (valid) atomicMax(&g_glb_win[cell], i);
    }
    out_valid[i] = valid ? 1.0f : 0.0f;
    out_near[i]  = (inb && !valid) ? 1.0f : 0.0f;
}

// --------------------------------------------------------------------------
// 4a) resolve current_volume only (needs g_cur_win; runs concurrently with
//     k_glb chain). One thread per float4 slot, fully coalesced stores.
// --------------------------------------------------------------------------
__global__ void k_resolve_cv(const float4* __restrict__ cur_vals,   // [N_CUR*6]
                             float* __restrict__ out)
{
    int tid = blockIdx.x * blockDim.x + threadIdx.x;
    if (tid >= NCELLS * NC4) return;
    int cell = tid / NC4;
    int q    = tid - cell * NC4;

    int wc = g_cur_win[cell];
    float4 v = (wc >= 0) ? __ldg(&cur_vals[wc * NC4 + q])
                         : make_float4(0.f, 0.f, 0.f, 0.f);
    reinterpret_cast<float4*>(out + OFF_CV)[tid] = v;
}

// --------------------------------------------------------------------------
// 4b) resolve global_volume + updated_mask + target_volume (needs k_glb).
// --------------------------------------------------------------------------
__global__ void k_resolve_gv(const float4* __restrict__ glb_vals,   // [N_GLB*6]
                             const float*  __restrict__ g_tsdf,     // [N_GTGT]
                             const float*  __restrict__ c_tsdf,     // [N_TGT]
                             float* __restrict__ out)
{
    int tid = blockIdx.x * blockDim.x + threadIdx.x;
    if (tid >= NCELLS * NC4) return;
    int cell = tid / NC4;
    int q    = tid - cell * NC4;

    int wg = g_glb_win[cell];
    float4 v = (wg >= 0) ? __ldg(&glb_vals[wg * NC4 + q])
                         : make_float4(0.f, 0.f, 0.f, 0.f);
    reinterpret_cast<float4*>(out + OFF_GV)[tid] = v;

    if (q == 0) {
        out[OFF_UPD + cell] = (wg >= 0 || g_occ[cell]) ? 1.0f : 0.0f;
        int wt = g_tgt_win[cell];
        float tv = 1.0f;
        if (wt >= 0)
            tv = (wt < N_GTGT) ? __ldg(&g_tsdf[wt]) : __ldg(&c_tsdf[wt - N_GTGT]);
        out[OFF_TV + cell] = tv;
    }
}

// ---------------------------------------------------------------------------
extern "C" void kernel_launch(void* const* d_in, const int* in_sizes, int n_in,
                              void* d_out, int out_size)
{
    const int*   current_coords     = (const int*)  d_in[0];
    const float* current_values     = (const float*)d_in[1];
    const int*   global_coords      = (const int*)  d_in[2];
    const float* global_value       = (const float*)d_in[3];
    const int*   coords_tgt_global  = (const int*)  d_in[4];
    const float* tsdf_target        = (const float*)d_in[5];
    const int*   global_coords_tgt  = (const int*)  d_in[6];
    const float* global_tsdf_target = (const float*)d_in[7];
    const int*   relative_origin    = (const int*)  d_in[8];
    const int*   grid_mask          = (const int*)  d_in[9];
    const int*   occupancy          = (const int*)  d_in[10];

    float* out = (float*)d_out;
    cudaStream_t sB = cudaStreamPerThread;

    static cudaEvent_t eScat, eB;
    static bool einit = false;
    if (!einit) {
        cudaEventCreateWithFlags(&eScat, cudaEventDisableTiming);
        cudaEventCreateWithFlags(&eB,    cudaEventDisableTiming);
        einit = true;
    }

    const int B = 256;
    const int N_SCAT1 = N_CUR + N_GTGT + N_TGT;

    // ---- stream 0: init -> fused scatter ----
    k_init<<<(NCELLS / 4 + B - 1) / B, B>>>();
    k_scat1<<<(N_SCAT1 + B - 1) / B, B>>>(current_coords, grid_mask, occupancy,
                                          global_coords_tgt, coords_tgt_global,
                                          relative_origin, out + OFF_VT);
    cudaEventRecord(eScat, 0);

    // ---- branch B: glb winner chain + gv/upd/tv resolve ----
    cudaStreamWaitEvent(sB, eScat, 0);
    k_glb<<<(N_GLB + B - 1) / B, B, 0, sB>>>(global_coords, relative_origin,
                                             out + OFF_VAL, out + OFF_NR);
    k_resolve_gv<<<(NCELLS * NC4 + B - 1) / B, B, 0, sB>>>(
        (const float4*)global_value, global_tsdf_target, tsdf_target, out);
    cudaEventRecord(eB, sB);

    // ---- stream 0 (concurrent with branch B): cv resolve ----
    k_resolve_cv<<<(NCELLS * NC4 + B - 1) / B, B>>>(
        (const float4*)current_values, out);

    // ---- join ----
    cudaStreamWaitEvent(0, eB, 0);
}

// round 7
// speedup vs baseline: 1.4858x; 1.4858x over previous
#include <cuda_runtime.h>
#include <cstdint>

// ---------------------------------------------------------------------------
// GlobalFusion: sparse->dense scatter fusion, DIM=96, C=24.
// Outputs (f32, concatenated in tuple order):
//   updated_mask   [96^3]            off 0
//   current_volume [96^3 * 24]       off 884736
//   global_volume  [96^3 * 24]       off 22118400
//   target_volume  [96^3]            off 43352064
//   valid          [300000]          off 44236800
//   valid_target   [200000]          off 44536800
//   near_mask      [300000]          off 44736800
//
// R7: serial pipeline (measured best structure) with a high-MLP monolithic
// resolve: each thread handles 2 cells x {cur,glb} = 4 independent
// winner->gather chains, stores fully coalesced.
// ---------------------------------------------------------------------------

#define DIMV   96
#define NCELLS (96 * 96 * 96)   // 884736
#define NC4    6                // 24 floats = 6 float4
#define HCELLS (NCELLS / 2)     // 442368
#define N_CUR  150000
#define N_GLB  300000
#define N_TGT  100000
#define N_GTGT 200000

#define OFF_UPD 0
#define OFF_CV  884736
#define OFF_GV  22118400
#define OFF_TV  43352064
#define OFF_VAL 44236800
#define OFF_VT  44536800
#define OFF_NR  44736800

// Scratch (static device globals; no allocation allowed)
__device__ int           g_cur_win[NCELLS];
__device__ int           g_glb_win[NCELLS];
__device__ int           g_tgt_win[NCELLS];
__device__ unsigned char g_valid_vol[NCELLS];
__device__ unsigned char g_occ[NCELLS];

// --------------------------------------------------------------------------
// 1) reset scratch (int4-vectorized)
// --------------------------------------------------------------------------
__global__ void k_init()
{
    int i = blockIdx.x * blockDim.x + threadIdx.x;           // NCELLS/4 threads
    if (i < NCELLS / 4) {
        int4 m1 = make_int4(-1, -1, -1, -1);
        reinterpret_cast<int4*>(g_cur_win)[i] = m1;
        reinterpret_cast<int4*>(g_glb_win)[i] = m1;
        reinterpret_cast<int4*>(g_tgt_win)[i] = m1;
        reinterpret_cast<uint*>(g_valid_vol)[i] = 0u;
        reinterpret_cast<uint*>(g_occ)[i] = 0u;
    }
}

// --------------------------------------------------------------------------
// 2) fused scatter: current-fragment rows + both target scatters.
//    JAX sequential-scatter semantics (last duplicate row wins) -> atomicMax
//    on row index; current-fragment target rows get priority N_GTGT+j so
//    they always beat the global target rows (torch cat order).
// --------------------------------------------------------------------------
__global__ void k_scat1(const int* __restrict__ cc,
                        const int* __restrict__ grid_mask,
                        const int* __restrict__ occupancy,
                        const int* __restrict__ gct,
                        const int* __restrict__ ct,
                        const int* __restrict__ org,
                        float* __restrict__ out_vt)
{
    int i = blockIdx.x * blockDim.x + threadIdx.x;

    if (i < N_CUR) {
        int x = cc[3 * i + 0];
        int y = cc[3 * i + 1];
        int z = cc[3 * i + 2];
        int cell = (x * DIMV + y) * DIMV + z;
        if (grid_mask[i]) g_valid_vol[cell] = 1;
        if (occupancy[i]) g_occ[cell] = 1;
        atomicMax(&g_cur_win[cell], i);
        return;
    }
    int t = i - N_CUR;
    if (t < N_GTGT) {
        int ox = __ldg(&org[0]), oy = __ldg(&org[1]), oz = __ldg(&org[2]);
        int x = gct[3 * t + 0] - ox;
        int y = gct[3 * t + 1] - oy;
        int z = gct[3 * t + 2] - oz;
        bool inb = ((unsigned)x < DIMV) && ((unsigned)y < DIMV) && ((unsigned)z < DIMV);
        out_vt[t] = inb ? 1.0f : 0.0f;
        if (inb) atomicMax(&g_tgt_win[(x * DIMV + y) * DIMV + z], t);
        return;
    }
    int j = t - N_GTGT;
    if (j < N_TGT) {
        int x = ct[3 * j + 0];
        int y = ct[3 * j + 1];
        int z = ct[3 * j + 2];
        atomicMax(&g_tgt_win[(x * DIMV + y) * DIMV + z], N_GTGT + j);
    }
}

// --------------------------------------------------------------------------
// 3) global-fragment rows: bounds + visibility gather, valid/near, glb winner
// --------------------------------------------------------------------------
__global__ void k_glb(const int* __restrict__ gc,
                      const int* __restrict__ org,
                      float* __restrict__ out_valid,
                      float* __restrict__ out_near)
{
    int i = blockIdx.x * blockDim.x + threadIdx.x;
    if (i >= N_GLB) return;
    int ox = __ldg(&org[0]), oy = __ldg(&org[1]), oz = __ldg(&org[2]);
    int x = gc[3 * i + 0] - ox;
    int y = gc[3 * i + 1] - oy;
    int z = gc[3 * i + 2] - oz;
    bool inb = ((unsigned)x < DIMV) && ((unsigned)y < DIMV) && ((unsigned)z < DIMV);
    bool valid = false;
    if (inb) {
        int cell = (x * DIMV + y) * DIMV + z;
        valid = (g_valid_vol[cell] != 0);
        if (valid) atomicMax(&g_glb_win[cell], i);
    }
    out_valid[i] = valid ? 1.0f : 0.0f;
    out_near[i]  = (inb && !valid) ? 1.0f : 0.0f;
}

// --------------------------------------------------------------------------
// 4) monolithic high-MLP resolve.
//    Thread t handles slot (cellA, q) and slot (cellB, q) with
//    cellB = cellA + HCELLS, for BOTH volumes: 4 independent winner loads,
//    then up to 4 independent random gathers, then 4 coalesced float4 stores.
//    q==0 lanes additionally emit updated_mask + target_volume for both cells.
// --------------------------------------------------------------------------
__global__ void k_resolve(const float4* __restrict__ cur_vals,   // [N_CUR*6]
                          const float4* __restrict__ glb_vals,   // [N_GLB*6]
                          const float*  __restrict__ g_tsdf,     // [N_GTGT]
                          const float*  __restrict__ c_tsdf,     // [N_TGT]
                          float* __restrict__ out)
{
    int tid = blockIdx.x * blockDim.x + threadIdx.x;
    if (tid >= HCELLS * NC4) return;
    int cellA = tid / NC4;
    int q     = tid - cellA * NC4;
    int cellB = cellA + HCELLS;
    int tidB  = tid + HCELLS * NC4;

    // ---- 4 independent winner loads (issue all before consuming) ----
    int wcA = g_cur_win[cellA];
    int wcB = g_cur_win[cellB];
    int wgA = g_glb_win[cellA];
    int wgB = g_glb_win[cellB];

    float4 zero = make_float4(0.f, 0.f, 0.f, 0.f);

    // ---- 4 independent gathers ----
    float4 cvA = (wcA >= 0) ? __ldg(&cur_vals[wcA * NC4 + q]) : zero;
    float4 cvB = (wcB >= 0) ? __ldg(&cur_vals[wcB * NC4 + q]) : zero;
    float4 gvA = (wgA >= 0) ? __ldg(&glb_vals[wgA * NC4 + q]) : zero;
    float4 gvB = (wgB >= 0) ? __ldg(&glb_vals[wgB * NC4 + q]) : zero;

    // ---- coalesced stores ----
    float4* out_cv = reinterpret_cast<float4*>(out + OFF_CV);
    float4* out_gv = reinterpret_cast<float4*>(out + OFF_GV);
    out_cv[tid]  = cvA;
    out_cv[tidB] = cvB;
    out_gv[tid]  = gvA;
    out_gv[tidB] = gvB;

    if (q == 0) {
        int wtA = g_tgt_win[cellA];
        int wtB = g_tgt_win[cellB];
        unsigned char occA = g_occ[cellA];
        unsigned char occB = g_occ[cellB];

        out[OFF_UPD + cellA] = (wgA >= 0 || occA) ? 1.0f : 0.0f;
        out[OFF_UPD + cellB] = (wgB >= 0 || occB) ? 1.0f : 0.0f;

        float tvA = 1.0f, tvB = 1.0f;
        if (wtA >= 0)
            tvA = (wtA < N_GTGT) ? __ldg(&g_tsdf[wtA]) : __ldg(&c_tsdf[wtA - N_GTGT]);
        if (wtB >= 0)
            tvB = (wtB < N_GTGT) ? __ldg(&g_tsdf[wtB]) : __ldg(&c_tsdf[wtB - N_GTGT]);
        out[OFF_TV + cellA] = tvA;
        out[OFF_TV + cellB] = tvB;
    }
}

// ---------------------------------------------------------------------------
extern "C" void kernel_launch(void* const* d_in, const int* in_sizes, int n_in,
                              void* d_out, int out_size)
{
    const int*   current_coords     = (const int*)  d_in[0];
    const float* current_values     = (const float*)d_in[1];
    const int*   global_coords      = (const int*)  d_in[2];
    const float* global_value       = (const float*)d_in[3];
    const int*   coords_tgt_global  = (const int*)  d_in[4];
    const float* tsdf_target        = (const float*)d_in[5];
    const int*   global_coords_tgt  = (const int*)  d_in[6];
    const float* global_tsdf_target = (const float*)d_in[7];
    const int*   relative_origin    = (const int*)  d_in[8];
    const int*   grid_mask          = (const int*)  d_in[9];
    const int*   occupancy          = (const int*)  d_in[10];

    float* out = (float*)d_out;

    const int B = 256;
    const int N_SCAT1 = N_CUR + N_GTGT + N_TGT;

    k_init<<<(NCELLS / 4 + B - 1) / B, B>>>();
    k_scat1<<<(N_SCAT1 + B - 1) / B, B>>>(current_coords, grid_mask, occupancy,
                                          global_coords_tgt, coords_tgt_global,
                                          relative_origin, out + OFF_VT);
    k_glb<<<(N_GLB + B - 1) / B, B>>>(global_coords, relative_origin,
                                      out + OFF_VAL, out + OFF_NR);
    k_resolve<<<(HCELLS * NC4 + B - 1) / B, B>>>(
        (const float4*)current_values, (const float4*)global_value,
        global_tsdf_target, tsdf_target, out);
}